// round 12
// baseline (speedup 1.0000x reference)
#include <cuda_runtime.h>
#include <cuda_bf16.h>
#include <cstdint>

#define T 48
#define E 32
#define C0 64
#define C1 64
#define H1 256
#define H2 128
#define NPRED 12
#define SEQS (16 * 2048)
#define NQ (SEQS / 4)

__device__ float g_M[4096];            // M = Wq . Wk^T  [j][ci]
__device__ float g_W1p[64 * 256];      // W1' = Wv . W1
__device__ float g_b1p[256];           // b1' = b1 + bv . W1
__device__ float g_WKBQ[64];
__device__ float g_WQBK[64];
__device__ float g_C0v[1];

// ---- kernel A smem byte offsets (4 seqs / iter) ----
#define O_WIN_H 0        // WinT [64n][40k] bf16, stride 80B
#define O_WIN_L 5120
#define O_WC_H  10240    // WcT 3 x [64n][72k] bf16, stride 144B, dt stride 9216
#define O_WC_L  37888
#define O_X_H   65536    // x [192r][40k] bf16, stride 80B   (reused as z1/z2 in tail)
#define O_X_L   80896
#define O_H_H   96256    // h padded [4][50][72] bf16, row stride 144B, seq stride 7200
#define O_H_L   125056
#define O_HC    153856   // hc fp32 [192][68]
#define O_LAST  206080   // fp32 [4][64]
#define O_QK    207104   // fp32 [4][64]  (reused as sR in tail)
#define O_SC    208128   // fp32 [192]
#define O_ATTN  208896   // fp32 [4][48]
#define O_C0    209664
#define O_WKBQ  209680
#define O_WQBK  209936
#define O_BIAS  210192   // fp32: bin@0 bc@64
#define O_M     210704   // fp32 [64][65]
#define SMEM_A  227344

// MLP scratch (reuses dead x-staging region in the tail)
#define O_Z1    O_X_H            // fp32 [4][264] = 4224 B
#define O_Z2    (O_X_H + 4352)   // fp32 [4][132] = 2112 B

// ---------------- warp MMA helpers ----------------
__device__ __forceinline__ uint32_t smem_u32(const void* p) {
    uint32_t a;
    asm("{ .reg .u64 t; cvta.to.shared.u64 t, %1; cvt.u32.u64 %0, t; }" : "=r"(a) : "l"(p));
    return a;
}
__device__ __forceinline__ void hmma(float* d, const uint32_t* a, const uint32_t* b) {
    asm volatile(
        "mma.sync.aligned.m16n8k16.row.col.f32.bf16.bf16.f32 "
        "{%0,%1,%2,%3}, {%4,%5,%6,%7}, {%8,%9}, {%0,%1,%2,%3};"
        : "+f"(d[0]), "+f"(d[1]), "+f"(d[2]), "+f"(d[3])
        : "r"(a[0]), "r"(a[1]), "r"(a[2]), "r"(a[3]), "r"(b[0]), "r"(b[1]));
}
__device__ __forceinline__ void ldA(uint32_t* f, uint32_t rowbase, int stride, int k0, int lane) {
    int g = lane >> 3;
    uint32_t addr = rowbase + (uint32_t)(((lane & 7) + ((g & 1) << 3)) * stride
                                         + (k0 + ((g >> 1) << 3)) * 2);
    asm volatile("ldmatrix.sync.aligned.m8n8.x4.shared.b16 {%0,%1,%2,%3}, [%4];"
                 : "=r"(f[0]), "=r"(f[1]), "=r"(f[2]), "=r"(f[3]) : "r"(addr));
}
__device__ __forceinline__ void ldB(uint32_t* f, uint32_t base, int stride, int cb, int k0, int lane) {
    uint32_t addr = base + (uint32_t)((cb + (lane & 7)) * stride + k0 * 2
                                      + (((lane >> 3) & 1) << 4));
    asm volatile("ldmatrix.sync.aligned.m8n8.x2.shared.b16 {%0,%1}, [%2];"
                 : "=r"(f[0]), "=r"(f[1]) : "r"(addr));
}
__device__ __forceinline__ void splitw(float a, float b, uint32_t& hw, uint32_t& lw) {
    __nv_bfloat162 H = __floats2bfloat162_rn(a, b);
    float2 F = __bfloat1622float2(H);
    __nv_bfloat162 L = __floats2bfloat162_rn(a - F.x, b - F.y);
    hw = *reinterpret_cast<uint32_t*>(&H);
    lw = *reinterpret_cast<uint32_t*>(&L);
}

// ---------------- init kernel: fold attention + ctx weights ----------------
__global__ void __launch_bounds__(256)
kernelM(const float* __restrict__ Wq, const float* __restrict__ bq,
        const float* __restrict__ Wk, const float* __restrict__ bk,
        const float* __restrict__ Wv, const float* __restrict__ bv,
        const float* __restrict__ W1, const float* __restrict__ b1)
{
    int idx = blockIdx.x * 256 + threadIdx.x;
    if (idx < 4096) {                       // M = Wq . Wk^T
        int j = idx >> 6, ci = idx & 63;
        float a = 0.f;
        #pragma unroll 8
        for (int co = 0; co < 64; co++) a += Wq[j * 64 + co] * Wk[ci * 64 + co];
        g_M[idx] = a;
    } else if (idx < 4096 + 16384) {        // W1' = Wv . W1
        int o = idx - 4096;
        int ci = o >> 8, n = o & 255;
        float a = 0.f;
        #pragma unroll 8
        for (int co = 0; co < 64; co++) a += Wv[ci * 64 + co] * W1[co * 256 + n];
        g_W1p[o] = a;
    } else if (idx < 20480 + 256) {         // b1' = b1 + bv . W1
        int n = idx - 20480;
        float a = b1[n];
        #pragma unroll 8
        for (int co = 0; co < 64; co++) a += bv[co] * W1[co * 256 + n];
        g_b1p[n] = a;
    } else if (idx < 20736 + 64) {          // WKBQ, WQBK
        int t2 = idx - 20736;
        float a = 0.f, b = 0.f;
        #pragma unroll 8
        for (int co = 0; co < 64; co++) {
            a += Wk[t2 * 64 + co] * bq[co];
            b += Wq[t2 * 64 + co] * bk[co];
        }
        g_WKBQ[t2] = a;
        g_WQBK[t2] = b;
    } else if (idx == 20800) {
        float c = 0.f;
        #pragma unroll 8
        for (int co = 0; co < 64; co++) c += bq[co] * bk[co];
        g_C0v[0] = c;
    }
}

// ---------------- Kernel A: fused everything (GEMMs + attention + MLP -> out) ----------------
__global__ void __launch_bounds__(256, 1)
kernelA(const float* __restrict__ x,
        const float* __restrict__ Win, const float* __restrict__ bin,
        const float* __restrict__ Wc,  const float* __restrict__ bc,
        const float* __restrict__ W2,  const float* __restrict__ b2,
        const float* __restrict__ W3,  const float* __restrict__ b3,
        float* __restrict__ out)
{
    extern __shared__ char smc[];
    const uint32_t smb = smem_u32(smc);
    const int tid  = threadIdx.x;
    const int wid  = tid >> 5;
    const int lane = tid & 31;
    const int cbase = wid * 8;

    float* sBias = (float*)(smc + O_BIAS);
    float* sLast = (float*)(smc + O_LAST);
    float* sQK   = (float*)(smc + O_QK);     // also sR in tail
    float* sSC   = (float*)(smc + O_SC);
    float* sAttn = (float*)(smc + O_ATTN);
    float* sC0   = (float*)(smc + O_C0);
    float* sWKBQ = (float*)(smc + O_WKBQ);
    float* sWQBK = (float*)(smc + O_WQBK);
    float* sHC   = (float*)(smc + O_HC);
    float* sM    = (float*)(smc + O_M);      // [64][65]
    float* sZ1   = (float*)(smc + O_Z1);     // [4][264]
    float* sZ2   = (float*)(smc + O_Z2);     // [4][132]

    // ---- stage weights ----
    for (int i = tid; i < 2048; i += 256) {
        int e = i >> 6, c = i & 63;
        float w = Win[i];
        __nv_bfloat16 h = __float2bfloat16(w);
        *(__nv_bfloat16*)(smc + O_WIN_H + c * 80 + e * 2) = h;
        *(__nv_bfloat16*)(smc + O_WIN_L + c * 80 + e * 2) =
            __float2bfloat16(w - __bfloat162float(h));
    }
    for (int i = tid; i < 12288; i += 256) {
        int dt = i >> 12, r = i & 4095, ci = r >> 6, co = r & 63;
        float w = Wc[i];
        __nv_bfloat16 h = __float2bfloat16(w);
        uint32_t o = dt * 9216 + co * 144 + ci * 2;
        *(__nv_bfloat16*)(smc + O_WC_H + o) = h;
        *(__nv_bfloat16*)(smc + O_WC_L + o) = __float2bfloat16(w - __bfloat162float(h));
    }
    for (int i = tid; i < 4096; i += 256) {
        int j = i >> 6, ci = i & 63;
        sM[j * 65 + ci] = g_M[i];
    }
    if (tid < 64) {
        sWKBQ[tid] = g_WKBQ[tid];
        sWQBK[tid] = g_WQBK[tid];
        sBias[tid]      = bin[tid];
        sBias[64 + tid] = bc[tid];
    }
    if (tid == 128) sC0[0] = g_C0v[0];
    for (int i = tid; i < 14400; i += 256) ((uint32_t*)(smc + O_H_H))[i] = 0;
    __syncthreads();

    // ---- prologue: stage x(quad0), GEMM1(quad0) -> h ----
    {
        const float4* xg = (const float4*)(x + (size_t)blockIdx.x * 4 * (T * E));
        for (int i = tid; i < 1536; i += 256) {
            float4 v = xg[i];
            int row = i >> 3, e4 = i & 7;
            uint32_t o = (uint32_t)(row * 80 + e4 * 8);
            uint32_t h0, l0, h1, l1;
            splitw(v.x, v.y, h0, l0);
            splitw(v.z, v.w, h1, l1);
            *(uint32_t*)(smc + O_X_H + o)     = h0;
            *(uint32_t*)(smc + O_X_H + o + 4) = h1;
            *(uint32_t*)(smc + O_X_L + o)     = l0;
            *(uint32_t*)(smc + O_X_L + o + 4) = l1;
        }
    }
    __syncthreads();
    {
        float acc[12][4] = {};
        #pragma unroll
        for (int k = 0; k < 2; k++) {
            int k0 = k * 16;
            uint32_t bh[2], bl[2];
            ldB(bh, smb + O_WIN_H, 80, cbase, k0, lane);
            ldB(bl, smb + O_WIN_L, 80, cbase, k0, lane);
            #pragma unroll
            for (int mt = 0; mt < 12; mt++) {
                uint32_t ah[4], al[4];
                ldA(ah, smb + O_X_H + mt * 16 * 80, 80, k0, lane);
                ldA(al, smb + O_X_L + mt * 16 * 80, 80, k0, lane);
                hmma(acc[mt], ah, bh);
                hmma(acc[mt], ah, bl);
                hmma(acc[mt], al, bh);
            }
        }
        int c = cbase + (lane & 3) * 2;
        float b0 = sBias[c], b1v = sBias[c + 1];
        #pragma unroll
        for (int mt = 0; mt < 12; mt++) {
            int s = mt / 3, j = mt % 3;
            int t0 = j * 16 + (lane >> 2), t1 = t0 + 8;
            uint32_t h0, l0, h1, l1;
            splitw(acc[mt][0] + b0, acc[mt][1] + b1v, h0, l0);
            splitw(acc[mt][2] + b0, acc[mt][3] + b1v, h1, l1);
            uint32_t o0 = (uint32_t)(s * 7200 + (t0 + 1) * 144 + c * 2);
            uint32_t o1 = (uint32_t)(s * 7200 + (t1 + 1) * 144 + c * 2);
            *(uint32_t*)(smc + O_H_H + o0) = h0;
            *(uint32_t*)(smc + O_H_L + o0) = l0;
            *(uint32_t*)(smc + O_H_H + o1) = h1;
            *(uint32_t*)(smc + O_H_L + o1) = l1;
        }
    }
    __syncthreads();

    // ---- main loop ----
    for (int quad = blockIdx.x; quad < NQ; quad += gridDim.x) {
        const int seq0 = quad * 4;
        const int nquad = quad + gridDim.x;
        const bool hasnext = nquad < NQ;

        float4 nx[6];
        if (hasnext) {
            const float4* xg = (const float4*)(x + (size_t)nquad * 4 * (T * E));
            #pragma unroll
            for (int j = 0; j < 6; j++) nx[j] = xg[tid + j * 256];
        }

        // ---- GEMM2: hc = relu(conv(h) + bc), fp32 [192][68] ----
        {
            float acc[12][4] = {};
            #pragma unroll
            for (int dt = 0; dt < 3; dt++) {
                #pragma unroll
                for (int k = 0; k < 4; k++) {
                    int k0 = k * 16;
                    uint32_t bh[2], bl[2];
                    ldB(bh, smb + O_WC_H + dt * 9216, 144, cbase, k0, lane);
                    ldB(bl, smb + O_WC_L + dt * 9216, 144, cbase, k0, lane);
                    #pragma unroll
                    for (int mt = 0; mt < 12; mt++) {
                        int s = mt / 3, j = mt % 3;
                        uint32_t rb = (uint32_t)(s * 7200 + (j * 16 + dt) * 144);
                        uint32_t ah[4], al[4];
                        ldA(ah, smb + O_H_H + rb, 144, k0, lane);
                        ldA(al, smb + O_H_L + rb, 144, k0, lane);
                        hmma(acc[mt], ah, bh);
                        hmma(acc[mt], ah, bl);
                        hmma(acc[mt], al, bh);
                    }
                }
            }
            int c = cbase + (lane & 3) * 2;
            float b0 = sBias[64 + c], b1v = sBias[64 + c + 1];
            #pragma unroll
            for (int mt = 0; mt < 12; mt++) {
                int s = mt / 3, j = mt % 3;
                int t0 = j * 16 + (lane >> 2), t1 = t0 + 8;
                int g0 = s * 48 + t0, g1 = s * 48 + t1;
                float v0 = fmaxf(acc[mt][0] + b0, 0.f), v1 = fmaxf(acc[mt][1] + b1v, 0.f);
                float v2 = fmaxf(acc[mt][2] + b0, 0.f), v3 = fmaxf(acc[mt][3] + b1v, 0.f);
                sHC[g0 * 68 + c]     = v0;
                sHC[g0 * 68 + c + 1] = v1;
                sHC[g1 * 68 + c]     = v2;
                sHC[g1 * 68 + c + 1] = v3;
                if (t1 == 47) {
                    sLast[s * 64 + c]     = v2;
                    sLast[s * 64 + c + 1] = v3;
                }
            }
        }

        if (hasnext) {
            #pragma unroll
            for (int j = 0; j < 6; j++) {
                float4 v = nx[j];
                int idx = tid + j * 256;
                int row = idx >> 3, e4 = idx & 7;
                uint32_t o = (uint32_t)(row * 80 + e4 * 8);
                uint32_t h0, l0, h1, l1;
                splitw(v.x, v.y, h0, l0);
                splitw(v.z, v.w, h1, l1);
                *(uint32_t*)(smc + O_X_H + o)     = h0;
                *(uint32_t*)(smc + O_X_H + o + 4) = h1;
                *(uint32_t*)(smc + O_X_L + o)     = l0;
                *(uint32_t*)(smc + O_X_L + o + 4) = l1;
            }
        }
        __syncthreads();

        // ---- GEMM1(next quad): compute only (x consumed here; region reused below) ----
        float acc1[12][4] = {};
        if (hasnext) {
            #pragma unroll
            for (int k = 0; k < 2; k++) {
                int k0 = k * 16;
                uint32_t bh[2], bl[2];
                ldB(bh, smb + O_WIN_H, 80, cbase, k0, lane);
                ldB(bl, smb + O_WIN_L, 80, cbase, k0, lane);
                #pragma unroll
                for (int mt = 0; mt < 12; mt++) {
                    uint32_t ah[4], al[4];
                    ldA(ah, smb + O_X_H + mt * 16 * 80, 80, k0, lane);
                    ldA(al, smb + O_X_L + mt * 16 * 80, 80, k0, lane);
                    hmma(acc1[mt], ah, bh);
                    hmma(acc1[mt], ah, bl);
                    hmma(acc1[mt], al, bh);
                }
            }
        }

        // ---- qk = M^T hc_last + wkbq (smem M) ----
        {
            int s = tid >> 6, c = tid & 63;
            const float* hl = sLast + s * 64;
            float a = sWKBQ[c];
            #pragma unroll 8
            for (int j = 0; j < 64; j++) a += hl[j] * sM[j * 65 + c];
            sQK[s * 64 + c] = a;
        }
        __syncthreads();

        // ---- raw scores: float4 dot over [68]-stride rows ----
        if (tid < 192) {
            int row = tid, s = row / 48;
            const float4* qk4 = (const float4*)(sQK + s * 64);
            const float4* hr4 = (const float4*)(sHC + row * 68);
            float p = 0.f;
            #pragma unroll
            for (int j = 0; j < 16; j++) {
                float4 a4 = qk4[j], b4 = hr4[j];
                p += a4.x * b4.x + a4.y * b4.y + a4.z * b4.z + a4.w * b4.w;
            }
            sSC[row] = p;
        }
        __syncthreads();

        // ---- softmax over 48 per seq (warp s), qb inline ----
        if (wid < 4) {
            const float* hl = sLast + wid * 64;
            float qb = hl[lane] * sWQBK[lane] + hl[lane + 32] * sWQBK[lane + 32];
            #pragma unroll
            for (int o = 16; o > 0; o >>= 1) qb += __shfl_xor_sync(0xffffffffu, qb, o);
            qb += sC0[0];
            int base = wid * 48;
            float a  = (sSC[base + lane] + qb) * 0.125f;
            float b2v = (lane < 16) ? (sSC[base + 32 + lane] + qb) * 0.125f : -1e30f;
            float m = fmaxf(a, b2v);
            #pragma unroll
            for (int o = 16; o > 0; o >>= 1) m = fmaxf(m, __shfl_xor_sync(0xffffffffu, m, o));
            float ea = __expf(a - m);
            float eb = (lane < 16) ? __expf(b2v - m) : 0.f;
            float sden = ea + eb;
            #pragma unroll
            for (int o = 16; o > 0; o >>= 1) sden += __shfl_xor_sync(0xffffffffu, sden, o);
            float inv = 1.f / sden;
            sAttn[base + lane] = ea * inv;
            if (lane < 16) sAttn[base + 32 + lane] = eb * inv;
        }
        __syncthreads();

        // ---- r = attn^T . hc -> sR (reuses sQK) ----
        {
            int s = tid >> 6, c = tid & 63;
            const float* at = sAttn + s * 48;
            const float* hb = sHC + s * 48 * 68 + c;
            float a = 0.f;
            #pragma unroll
            for (int t = 0; t < 48; t++) a += at[t] * hb[t * 68];
            sQK[s * 64 + c] = a;      // sR
        }
        __syncthreads();

        // ---- MLP layer1: z1[4][256] = relu(r @ W1' + b1') (W1' via L2) ----
        {
            int cg = tid >> 2, rr = tid & 3;       // cols cg*4.., row rr
            const float* rrow = sQK + rr * 64;
            float4 bb = __ldg((const float4*)&g_b1p[cg * 4]);
            float a0 = bb.x, a1 = bb.y, a2 = bb.z, a3 = bb.w;
            #pragma unroll 8
            for (int k = 0; k < 64; k++) {
                float4 w = __ldg((const float4*)&g_W1p[k * 256 + cg * 4]);
                float rv = rrow[k];
                a0 += rv * w.x; a1 += rv * w.y; a2 += rv * w.z; a3 += rv * w.w;
            }
            ((float4*)(sZ1 + rr * 264 + cg * 4))[0] =
                make_float4(fmaxf(a0, 0.f), fmaxf(a1, 0.f), fmaxf(a2, 0.f), fmaxf(a3, 0.f));
        }
        __syncthreads();

        // ---- MLP layer2: z2[4][128] = relu(z1 @ W2 + b2), K split x2 ----
        {
            int cg2 = tid >> 3, rr2 = (tid >> 1) & 3, kh = tid & 1;
            const float* z = sZ1 + rr2 * 264 + kh * 128;
            float a0 = 0.f, a1 = 0.f, a2 = 0.f, a3 = 0.f;
            if (!kh) {
                float4 bb = __ldg((const float4*)&b2[cg2 * 4]);
                a0 = bb.x; a1 = bb.y; a2 = bb.z; a3 = bb.w;
            }
            #pragma unroll 8
            for (int k = 0; k < 128; k++) {
                float4 w = __ldg((const float4*)&W2[(kh * 128 + k) * 128 + cg2 * 4]);
                float zv = z[k];
                a0 += zv * w.x; a1 += zv * w.y; a2 += zv * w.z; a3 += zv * w.w;
            }
            a0 += __shfl_xor_sync(0xffffffffu, a0, 1);
            a1 += __shfl_xor_sync(0xffffffffu, a1, 1);
            a2 += __shfl_xor_sync(0xffffffffu, a2, 1);
            a3 += __shfl_xor_sync(0xffffffffu, a3, 1);
            if (!kh)
                ((float4*)(sZ2 + rr2 * 132 + cg2 * 4))[0] =
                    make_float4(fmaxf(a0, 0.f), fmaxf(a1, 0.f), fmaxf(a2, 0.f), fmaxf(a3, 0.f));
        }
        __syncthreads();

        // ---- MLP layer3: pred = z2 @ W3 + b3 -> transposed out ----
        if (tid < 48) {
            int r2 = tid / 12, p = tid % 12;
            const float* zr = sZ2 + r2 * 132;
            float a = __ldg(&b3[p]);
            #pragma unroll 16
            for (int f = 0; f < 128; f++) a += zr[f] * __ldg(&W3[f * NPRED + p]);
            int seqr = seq0 + r2;
            int bb = seqr >> 11;
            int nn = seqr & 2047;
            out[(size_t)bb * (NPRED * 2048) + p * 2048 + nn] = a;
        }

        // ---- ep1(next quad) ----
        if (hasnext) {
            int c = cbase + (lane & 3) * 2;
            float b0 = sBias[c], b1v = sBias[c + 1];
            #pragma unroll
            for (int mt = 0; mt < 12; mt++) {
                int s = mt / 3, j = mt % 3;
                int t0 = j * 16 + (lane >> 2), t1 = t0 + 8;
                uint32_t h0, l0, h1, l1;
                splitw(acc1[mt][0] + b0, acc1[mt][1] + b1v, h0, l0);
                splitw(acc1[mt][2] + b0, acc1[mt][3] + b1v, h1, l1);
                uint32_t o0 = (uint32_t)(s * 7200 + (t0 + 1) * 144 + c * 2);
                uint32_t o1 = (uint32_t)(s * 7200 + (t1 + 1) * 144 + c * 2);
                *(uint32_t*)(smc + O_H_H + o0) = h0;
                *(uint32_t*)(smc + O_H_L + o0) = l0;
                *(uint32_t*)(smc + O_H_H + o1) = h1;
                *(uint32_t*)(smc + O_H_L + o1) = l1;
            }
        }
        __syncthreads();
    }
}

extern "C" void kernel_launch(void* const* d_in, const int* in_sizes, int n_in,
                              void* d_out, int out_size)
{
    const float* x     = (const float*)d_in[0];
    const float* W_in  = (const float*)d_in[1];
    const float* b_in  = (const float*)d_in[2];
    const float* W_c   = (const float*)d_in[3];
    const float* b_c   = (const float*)d_in[4];
    const float* Wq    = (const float*)d_in[5];
    const float* bq    = (const float*)d_in[6];
    const float* Wk    = (const float*)d_in[7];
    const float* bk    = (const float*)d_in[8];
    const float* Wv    = (const float*)d_in[9];
    const float* bv    = (const float*)d_in[10];
    const float* W1    = (const float*)d_in[11];
    const float* b1    = (const float*)d_in[12];
    const float* W2    = (const float*)d_in[13];
    const float* b2    = (const float*)d_in[14];
    const float* W3    = (const float*)d_in[15];
    const float* b3    = (const float*)d_in[16];

    cudaFuncSetAttribute(kernelA, cudaFuncAttributeMaxDynamicSharedMemorySize, SMEM_A);

    kernelM<<<82, 256>>>(Wq, bq, Wk, bk, Wv, bv, W1, b1);
    kernelA<<<152, 256, SMEM_A>>>(x, W_in, b_in, W_c, b_c, W2, b2, W3, b3, (float*)d_out);
}

// round 13
// speedup vs baseline: 1.4562x; 1.4562x over previous
#include <cuda_runtime.h>
#include <cuda_bf16.h>
#include <cstdint>

#define T 48
#define E 32
#define C0 64
#define C1 64
#define H1 256
#define H2 128
#define NPRED 12
#define SEQS (16 * 2048)
#define NQ (SEQS / 4)

__device__ float g_last[SEQS * C1];    // holds r (ctx folded into MLP weights)
__device__ float g_M[4096];            // M = Wq . Wk^T  [j][ci]
__device__ float g_W1p[64 * 256];      // W1' = Wv . W1
__device__ float g_b1p[256];           // b1' = b1 + bv . W1
__device__ float g_WKBQ[64];
__device__ float g_WQBK[64];
__device__ float g_C0v[1];

// ---- kernel A smem byte offsets (4 seqs / iter) ----
#define O_WIN_H 0        // WinT [64n][40k] bf16, stride 80B
#define O_WIN_L 5120
#define O_WC_H  10240    // WcT 3 x [64n][72k] bf16, stride 144B, dt stride 9216
#define O_WC_L  37888
#define O_X_H   65536    // x [192r][40k] bf16, stride 80B
#define O_X_L   80896
#define O_H_H   96256    // h padded [4][50][72] bf16, row stride 144B, seq stride 7200
#define O_H_L   125056
#define O_HC    153856   // hc fp32 [192][68]
#define O_LAST  206080   // fp32 [4][64]
#define O_QK    207104   // fp32 [4][64]
#define O_SC    208128   // fp32 [192]
#define O_ATTN  208896   // fp32 [4][48]
#define O_C0    209664
#define O_WKBQ  209680
#define O_WQBK  209936
#define O_BIAS  210192   // fp32: bin@0 bc@64
#define O_M     210704   // fp32 [64][65]
#define SMEM_A  227344

// ---------------- warp MMA helpers ----------------
__device__ __forceinline__ uint32_t smem_u32(const void* p) {
    uint32_t a;
    asm("{ .reg .u64 t; cvta.to.shared.u64 t, %1; cvt.u32.u64 %0, t; }" : "=r"(a) : "l"(p));
    return a;
}
__device__ __forceinline__ void hmma(float* d, const uint32_t* a, const uint32_t* b) {
    asm volatile(
        "mma.sync.aligned.m16n8k16.row.col.f32.bf16.bf16.f32 "
        "{%0,%1,%2,%3}, {%4,%5,%6,%7}, {%8,%9}, {%0,%1,%2,%3};"
        : "+f"(d[0]), "+f"(d[1]), "+f"(d[2]), "+f"(d[3])
        : "r"(a[0]), "r"(a[1]), "r"(a[2]), "r"(a[3]), "r"(b[0]), "r"(b[1]));
}
__device__ __forceinline__ void ldA(uint32_t* f, uint32_t rowbase, int stride, int k0, int lane) {
    int g = lane >> 3;
    uint32_t addr = rowbase + (uint32_t)(((lane & 7) + ((g & 1) << 3)) * stride
                                         + (k0 + ((g >> 1) << 3)) * 2);
    asm volatile("ldmatrix.sync.aligned.m8n8.x4.shared.b16 {%0,%1,%2,%3}, [%4];"
                 : "=r"(f[0]), "=r"(f[1]), "=r"(f[2]), "=r"(f[3]) : "r"(addr));
}
__device__ __forceinline__ void ldB(uint32_t* f, uint32_t base, int stride, int cb, int k0, int lane) {
    uint32_t addr = base + (uint32_t)((cb + (lane & 7)) * stride + k0 * 2
                                      + (((lane >> 3) & 1) << 4));
    asm volatile("ldmatrix.sync.aligned.m8n8.x2.shared.b16 {%0,%1}, [%2];"
                 : "=r"(f[0]), "=r"(f[1]) : "r"(addr));
}
__device__ __forceinline__ void splitw(float a, float b, uint32_t& hw, uint32_t& lw) {
    __nv_bfloat162 H = __floats2bfloat162_rn(a, b);
    float2 F = __bfloat1622float2(H);
    __nv_bfloat162 L = __floats2bfloat162_rn(a - F.x, b - F.y);
    hw = *reinterpret_cast<uint32_t*>(&H);
    lw = *reinterpret_cast<uint32_t*>(&L);
}

// ---------------- init kernel: fold attention + ctx weights ----------------
__global__ void __launch_bounds__(256)
kernelM(const float* __restrict__ Wq, const float* __restrict__ bq,
        const float* __restrict__ Wk, const float* __restrict__ bk,
        const float* __restrict__ Wv, const float* __restrict__ bv,
        const float* __restrict__ W1, const float* __restrict__ b1)
{
    int idx = blockIdx.x * 256 + threadIdx.x;
    if (idx < 4096) {                       // M = Wq . Wk^T
        int j = idx >> 6, ci = idx & 63;
        float a = 0.f;
        #pragma unroll 8
        for (int co = 0; co < 64; co++) a += Wq[j * 64 + co] * Wk[ci * 64 + co];
        g_M[idx] = a;
    } else if (idx < 4096 + 16384) {        // W1' = Wv . W1
        int o = idx - 4096;
        int ci = o >> 8, n = o & 255;
        float a = 0.f;
        #pragma unroll 8
        for (int co = 0; co < 64; co++) a += Wv[ci * 64 + co] * W1[co * 256 + n];
        g_W1p[o] = a;
    } else if (idx < 20480 + 256) {         // b1' = b1 + bv . W1
        int n = idx - 20480;
        float a = b1[n];
        #pragma unroll 8
        for (int co = 0; co < 64; co++) a += bv[co] * W1[co * 256 + n];
        g_b1p[n] = a;
    } else if (idx < 20736 + 64) {          // WKBQ, WQBK
        int t2 = idx - 20736;
        float a = 0.f, b = 0.f;
        #pragma unroll 8
        for (int co = 0; co < 64; co++) {
            a += Wk[t2 * 64 + co] * bq[co];
            b += Wq[t2 * 64 + co] * bk[co];
        }
        g_WKBQ[t2] = a;
        g_WQBK[t2] = b;
    } else if (idx == 20800) {
        float c = 0.f;
        #pragma unroll 8
        for (int co = 0; co < 64; co++) c += bq[co] * bk[co];
        g_C0v[0] = c;
    }
}

// ---------------- Kernel A: rotated pipeline, 4 seqs/iter, r-output (round-11 proven) ----------------
__global__ void __launch_bounds__(256, 1)
kernelA(const float* __restrict__ x,
        const float* __restrict__ Win, const float* __restrict__ bin,
        const float* __restrict__ Wc,  const float* __restrict__ bc)
{
    extern __shared__ char smc[];
    const uint32_t smb = smem_u32(smc);
    const int tid  = threadIdx.x;
    const int wid  = tid >> 5;
    const int lane = tid & 31;
    const int cbase = wid * 8;

    float* sBias = (float*)(smc + O_BIAS);
    float* sLast = (float*)(smc + O_LAST);
    float* sQK   = (float*)(smc + O_QK);
    float* sSC   = (float*)(smc + O_SC);
    float* sAttn = (float*)(smc + O_ATTN);
    float* sC0   = (float*)(smc + O_C0);
    float* sWKBQ = (float*)(smc + O_WKBQ);
    float* sWQBK = (float*)(smc + O_WQBK);
    float* sHC   = (float*)(smc + O_HC);
    float* sM    = (float*)(smc + O_M);      // [64][65]

    // ---- stage weights ----
    for (int i = tid; i < 2048; i += 256) {
        int e = i >> 6, c = i & 63;
        float w = Win[i];
        __nv_bfloat16 h = __float2bfloat16(w);
        *(__nv_bfloat16*)(smc + O_WIN_H + c * 80 + e * 2) = h;
        *(__nv_bfloat16*)(smc + O_WIN_L + c * 80 + e * 2) =
            __float2bfloat16(w - __bfloat162float(h));
    }
    for (int i = tid; i < 12288; i += 256) {
        int dt = i >> 12, r = i & 4095, ci = r >> 6, co = r & 63;
        float w = Wc[i];
        __nv_bfloat16 h = __float2bfloat16(w);
        uint32_t o = dt * 9216 + co * 144 + ci * 2;
        *(__nv_bfloat16*)(smc + O_WC_H + o) = h;
        *(__nv_bfloat16*)(smc + O_WC_L + o) = __float2bfloat16(w - __bfloat162float(h));
    }
    for (int i = tid; i < 4096; i += 256) {     // M -> smem, re-stride to 65
        int j = i >> 6, ci = i & 63;
        sM[j * 65 + ci] = g_M[i];
    }
    if (tid < 64) {
        sWKBQ[tid] = g_WKBQ[tid];
        sWQBK[tid] = g_WQBK[tid];
        sBias[tid]      = bin[tid];
        sBias[64 + tid] = bc[tid];
    }
    if (tid == 128) sC0[0] = g_C0v[0];
    for (int i = tid; i < 14400; i += 256) ((uint32_t*)(smc + O_H_H))[i] = 0;
    __syncthreads();

    // ---- prologue: stage x(quad0), GEMM1(quad0) -> h ----
    {
        const float4* xg = (const float4*)(x + (size_t)blockIdx.x * 4 * (T * E));
        for (int i = tid; i < 1536; i += 256) {
            float4 v = xg[i];
            int row = i >> 3, e4 = i & 7;
            uint32_t o = (uint32_t)(row * 80 + e4 * 8);
            uint32_t h0, l0, h1, l1;
            splitw(v.x, v.y, h0, l0);
            splitw(v.z, v.w, h1, l1);
            *(uint32_t*)(smc + O_X_H + o)     = h0;
            *(uint32_t*)(smc + O_X_H + o + 4) = h1;
            *(uint32_t*)(smc + O_X_L + o)     = l0;
            *(uint32_t*)(smc + O_X_L + o + 4) = l1;
        }
    }
    __syncthreads();
    {
        float acc[12][4] = {};
        #pragma unroll
        for (int k = 0; k < 2; k++) {
            int k0 = k * 16;
            uint32_t bh[2], bl[2];
            ldB(bh, smb + O_WIN_H, 80, cbase, k0, lane);
            ldB(bl, smb + O_WIN_L, 80, cbase, k0, lane);
            #pragma unroll
            for (int mt = 0; mt < 12; mt++) {
                uint32_t ah[4], al[4];
                ldA(ah, smb + O_X_H + mt * 16 * 80, 80, k0, lane);
                ldA(al, smb + O_X_L + mt * 16 * 80, 80, k0, lane);
                hmma(acc[mt], ah, bh);
                hmma(acc[mt], ah, bl);
                hmma(acc[mt], al, bh);
            }
        }
        int c = cbase + (lane & 3) * 2;
        float b0 = sBias[c], b1v = sBias[c + 1];
        #pragma unroll
        for (int mt = 0; mt < 12; mt++) {
            int s = mt / 3, j = mt % 3;
            int t0 = j * 16 + (lane >> 2), t1 = t0 + 8;
            uint32_t h0, l0, h1, l1;
            splitw(acc[mt][0] + b0, acc[mt][1] + b1v, h0, l0);
            splitw(acc[mt][2] + b0, acc[mt][3] + b1v, h1, l1);
            uint32_t o0 = (uint32_t)(s * 7200 + (t0 + 1) * 144 + c * 2);
            uint32_t o1 = (uint32_t)(s * 7200 + (t1 + 1) * 144 + c * 2);
            *(uint32_t*)(smc + O_H_H + o0) = h0;
            *(uint32_t*)(smc + O_H_L + o0) = l0;
            *(uint32_t*)(smc + O_H_H + o1) = h1;
            *(uint32_t*)(smc + O_H_L + o1) = l1;
        }
    }
    __syncthreads();

    // ---- main loop ----
    for (int quad = blockIdx.x; quad < NQ; quad += gridDim.x) {
        const int seq0 = quad * 4;
        const int nquad = quad + gridDim.x;
        const bool hasnext = nquad < NQ;

        float4 nx[6];
        if (hasnext) {
            const float4* xg = (const float4*)(x + (size_t)nquad * 4 * (T * E));
            #pragma unroll
            for (int j = 0; j < 6; j++) nx[j] = xg[tid + j * 256];
        }

        // ---- GEMM2: hc = relu(conv(h) + bc), fp32 [192][68] ----
        {
            float acc[12][4] = {};
            #pragma unroll
            for (int dt = 0; dt < 3; dt++) {
                #pragma unroll
                for (int k = 0; k < 4; k++) {
                    int k0 = k * 16;
                    uint32_t bh[2], bl[2];
                    ldB(bh, smb + O_WC_H + dt * 9216, 144, cbase, k0, lane);
                    ldB(bl, smb + O_WC_L + dt * 9216, 144, cbase, k0, lane);
                    #pragma unroll
                    for (int mt = 0; mt < 12; mt++) {
                        int s = mt / 3, j = mt % 3;
                        uint32_t rb = (uint32_t)(s * 7200 + (j * 16 + dt) * 144);
                        uint32_t ah[4], al[4];
                        ldA(ah, smb + O_H_H + rb, 144, k0, lane);
                        ldA(al, smb + O_H_L + rb, 144, k0, lane);
                        hmma(acc[mt], ah, bh);
                        hmma(acc[mt], ah, bl);
                        hmma(acc[mt], al, bh);
                    }
                }
            }
            int c = cbase + (lane & 3) * 2;
            float b0 = sBias[64 + c], b1v = sBias[64 + c + 1];
            #pragma unroll
            for (int mt = 0; mt < 12; mt++) {
                int s = mt / 3, j = mt % 3;
                int t0 = j * 16 + (lane >> 2), t1 = t0 + 8;
                int g0 = s * 48 + t0, g1 = s * 48 + t1;
                float v0 = fmaxf(acc[mt][0] + b0, 0.f), v1 = fmaxf(acc[mt][1] + b1v, 0.f);
                float v2 = fmaxf(acc[mt][2] + b0, 0.f), v3 = fmaxf(acc[mt][3] + b1v, 0.f);
                sHC[g0 * 68 + c]     = v0;
                sHC[g0 * 68 + c + 1] = v1;
                sHC[g1 * 68 + c]     = v2;
                sHC[g1 * 68 + c + 1] = v3;
                if (t1 == 47) {
                    sLast[s * 64 + c]     = v2;
                    sLast[s * 64 + c + 1] = v3;
                }
            }
        }

        if (hasnext) {
            #pragma unroll
            for (int j = 0; j < 6; j++) {
                float4 v = nx[j];
                int idx = tid + j * 256;
                int row = idx >> 3, e4 = idx & 7;
                uint32_t o = (uint32_t)(row * 80 + e4 * 8);
                uint32_t h0, l0, h1, l1;
                splitw(v.x, v.y, h0, l0);
                splitw(v.z, v.w, h1, l1);
                *(uint32_t*)(smc + O_X_H + o)     = h0;
                *(uint32_t*)(smc + O_X_H + o + 4) = h1;
                *(uint32_t*)(smc + O_X_L + o)     = l0;
                *(uint32_t*)(smc + O_X_L + o + 4) = l1;
            }
        }
        __syncthreads();

        // ---- GEMM1(next quad): compute only ----
        float acc1[12][4] = {};
        if (hasnext) {
            #pragma unroll
            for (int k = 0; k < 2; k++) {
                int k0 = k * 16;
                uint32_t bh[2], bl[2];
                ldB(bh, smb + O_WIN_H, 80, cbase, k0, lane);
                ldB(bl, smb + O_WIN_L, 80, cbase, k0, lane);
                #pragma unroll
                for (int mt = 0; mt < 12; mt++) {
                    uint32_t ah[4], al[4];
                    ldA(ah, smb + O_X_H + mt * 16 * 80, 80, k0, lane);
                    ldA(al, smb + O_X_L + mt * 16 * 80, 80, k0, lane);
                    hmma(acc1[mt], ah, bh);
                    hmma(acc1[mt], ah, bl);
                    hmma(acc1[mt], al, bh);
                }
            }
        }

        // ---- qk = M^T hc_last + wkbq (smem M) ----
        {
            int s = tid >> 6, c = tid & 63;
            const float* hl = sLast + s * 64;
            float a = sWKBQ[c];
            #pragma unroll 8
            for (int j = 0; j < 64; j++) a += hl[j] * sM[j * 65 + c];
            sQK[s * 64 + c] = a;
        }
        __syncthreads();

        // ---- raw scores: float4 dot over [68]-stride rows ----
        if (tid < 192) {
            int row = tid, s = row / 48;
            const float4* qk4 = (const float4*)(sQK + s * 64);
            const float4* hr4 = (const float4*)(sHC + row * 68);
            float p = 0.f;
            #pragma unroll
            for (int j = 0; j < 16; j++) {
                float4 a4 = qk4[j], b4 = hr4[j];
                p += a4.x * b4.x + a4.y * b4.y + a4.z * b4.z + a4.w * b4.w;
            }
            sSC[row] = p;
        }
        __syncthreads();

        // ---- softmax over 48 per seq (warp s), qb inline ----
        if (wid < 4) {
            const float* hl = sLast + wid * 64;
            float qb = hl[lane] * sWQBK[lane] + hl[lane + 32] * sWQBK[lane + 32];
            #pragma unroll
            for (int o = 16; o > 0; o >>= 1) qb += __shfl_xor_sync(0xffffffffu, qb, o);
            qb += sC0[0];
            int base = wid * 48;
            float a  = (sSC[base + lane] + qb) * 0.125f;
            float b2 = (lane < 16) ? (sSC[base + 32 + lane] + qb) * 0.125f : -1e30f;
            float m = fmaxf(a, b2);
            #pragma unroll
            for (int o = 16; o > 0; o >>= 1) m = fmaxf(m, __shfl_xor_sync(0xffffffffu, m, o));
            float ea = __expf(a - m);
            float eb = (lane < 16) ? __expf(b2 - m) : 0.f;
            float sden = ea + eb;
            #pragma unroll
            for (int o = 16; o > 0; o >>= 1) sden += __shfl_xor_sync(0xffffffffu, sden, o);
            float inv = 1.f / sden;
            sAttn[base + lane] = ea * inv;
            if (lane < 16) sAttn[base + 32 + lane] = eb * inv;
        }
        __syncthreads();

        // ---- r = attn^T . hc  -> g_last directly (ctx folded into MLP) ----
        {
            int s = tid >> 6, c = tid & 63;
            const float* at = sAttn + s * 48;
            const float* hb = sHC + s * 48 * 68 + c;
            float a = 0.f;
            #pragma unroll
            for (int t = 0; t < 48; t++) a += at[t] * hb[t * 68];
            g_last[(size_t)(seq0 + s) * 64 + c] = a;
        }

        // ---- ep1(next quad) ----
        if (hasnext) {
            int c = cbase + (lane & 3) * 2;
            float b0 = sBias[c], b1v = sBias[c + 1];
            #pragma unroll
            for (int mt = 0; mt < 12; mt++) {
                int s = mt / 3, j = mt % 3;
                int t0 = j * 16 + (lane >> 2), t1 = t0 + 8;
                uint32_t h0, l0, h1, l1;
                splitw(acc1[mt][0] + b0, acc1[mt][1] + b1v, h0, l0);
                splitw(acc1[mt][2] + b0, acc1[mt][3] + b1v, h1, l1);
                uint32_t o0 = (uint32_t)(s * 7200 + (t0 + 1) * 144 + c * 2);
                uint32_t o1 = (uint32_t)(s * 7200 + (t1 + 1) * 144 + c * 2);
                *(uint32_t*)(smc + O_H_H + o0) = h0;
                *(uint32_t*)(smc + O_H_L + o0) = l0;
                *(uint32_t*)(smc + O_H_H + o1) = h1;
                *(uint32_t*)(smc + O_H_L + o1) = l1;
            }
        }
        __syncthreads();
    }
}

// ---------------- Kernel B: MLP, 512 threads for latency hiding ----------------
#define SMEM_B_FLOATS 56880

__global__ void __launch_bounds__(512, 1)
kernelB(const float* __restrict__ W2, const float* __restrict__ b2,
        const float* __restrict__ W3, const float* __restrict__ b3,
        float* __restrict__ out)
{
    extern __shared__ float sm[];
    float* sW1 = sm;
    float* sW2 = sm + 16384;
    float* sb1 = sm + 49152;
    float* sb2 = sm + 49408;
    float* sb3 = sm + 49536;
    float* sIn = sm + 49552;   // [16][65]
    float* sZ1 = sm + 50592;   // [16][261]
    float* sZ2 = sm + 54768;   // [16][132]

    const int tid = threadIdx.x;

    for (int i = tid; i < 16384; i += 512) sW1[i] = g_W1p[i];
    for (int i = tid; i < 32768; i += 512) sW2[i] = W2[i];
    if (tid < 256) sb1[tid] = g_b1p[tid];
    else if (tid < 384) sb2[tid - 256] = b2[tid - 256];
    else if (tid < 396) sb3[tid - 384] = b3[tid - 384];
    __syncthreads();

    // layer1: col group c4 = tid&63 (4 cols), rows r0 and r0+8 (r0 = tid>>6, 0..7)
    const int l1_c4 = tid & 63;
    const int l1_r  = tid >> 6;
    // layer2: col group c4 = tid&31 (4 cols of 128), row = tid>>5 (0..15)
    const int l2_c4 = tid & 31;
    const int l2_r  = tid >> 5;

    for (int base = blockIdx.x * 16; base < SEQS; base += gridDim.x * 16) {
        // stage 16 rows of g_last -> sIn [16][65]
        if (tid < 256) {
            float4 v = ((const float4*)(g_last + (size_t)base * C1))[tid];
            int row = tid >> 4, e4 = tid & 15;
            float* d = sIn + row * 65 + e4 * 4;
            d[0] = v.x; d[1] = v.y; d[2] = v.z; d[3] = v.w;
        }
        __syncthreads();

        // ---- z1 = relu(in @ W1' + b1'): 16 x 256, 2 rows x 4 cols / thread ----
        {
            float4 bb = ((const float4*)sb1)[l1_c4];
            float a0[4] = {bb.x, bb.y, bb.z, bb.w};
            float a1[4] = {bb.x, bb.y, bb.z, bb.w};
            const float* in0 = sIn + l1_r * 65;
            const float* in1 = sIn + (l1_r + 8) * 65;
            #pragma unroll 8
            for (int f = 0; f < 64; f++) {
                float4 w = ((const float4*)(sW1 + f * H1))[l1_c4];
                float x0 = in0[f];
                float x1 = in1[f];
                a0[0] += x0 * w.x; a0[1] += x0 * w.y; a0[2] += x0 * w.z; a0[3] += x0 * w.w;
                a1[0] += x1 * w.x; a1[1] += x1 * w.y; a1[2] += x1 * w.z; a1[3] += x1 * w.w;
            }
            float* d0 = sZ1 + l1_r * 261 + l1_c4 * 4;
            float* d1 = sZ1 + (l1_r + 8) * 261 + l1_c4 * 4;
            d0[0] = fmaxf(a0[0], 0.f); d0[1] = fmaxf(a0[1], 0.f);
            d0[2] = fmaxf(a0[2], 0.f); d0[3] = fmaxf(a0[3], 0.f);
            d1[0] = fmaxf(a1[0], 0.f); d1[1] = fmaxf(a1[1], 0.f);
            d1[2] = fmaxf(a1[2], 0.f); d1[3] = fmaxf(a1[3], 0.f);
        }
        __syncthreads();

        // ---- z2 = relu(z1 @ W2 + b2): 16 x 128, 1 row x 4 cols / thread ----
        {
            float4 bb = ((const float4*)sb2)[l2_c4];
            float a[4] = {bb.x, bb.y, bb.z, bb.w};
            const float* zr = sZ1 + l2_r * 261;
            #pragma unroll 8
            for (int f = 0; f < 256; f++) {
                float4 w = ((const float4*)(sW2 + f * H2))[l2_c4];
                float z = zr[f];
                a[0] += z * w.x; a[1] += z * w.y; a[2] += z * w.z; a[3] += z * w.w;
            }
            ((float4*)(sZ2 + l2_r * 132))[l2_c4] =
                make_float4(fmaxf(a[0], 0.f), fmaxf(a[1], 0.f), fmaxf(a[2], 0.f), fmaxf(a[3], 0.f));
        }
        __syncthreads();

        // ---- pred = z2 @ W3 + b3: 16 x 12, transposed write; W3 via L1 ----
        if (tid < 192) {
            int r = tid / 12, p = tid % 12;
            const float* zr = sZ2 + r * 132;
            float a = sb3[p];
            #pragma unroll 16
            for (int f = 0; f < 128; f++) a += zr[f] * __ldg(&W3[f * NPRED + p]);
            int seqr = base + r;
            int bb = seqr >> 11;
            int nn = seqr & 2047;
            out[(size_t)bb * (NPRED * 2048) + p * 2048 + nn] = a;
        }
        __syncthreads();
    }
}

extern "C" void kernel_launch(void* const* d_in, const int* in_sizes, int n_in,
                              void* d_out, int out_size)
{
    const float* x     = (const float*)d_in[0];
    const float* W_in  = (const float*)d_in[1];
    const float* b_in  = (const float*)d_in[2];
    const float* W_c   = (const float*)d_in[3];
    const float* b_c   = (const float*)d_in[4];
    const float* Wq    = (const float*)d_in[5];
    const float* bq    = (const float*)d_in[6];
    const float* Wk    = (const float*)d_in[7];
    const float* bk    = (const float*)d_in[8];
    const float* Wv    = (const float*)d_in[9];
    const float* bv    = (const float*)d_in[10];
    const float* W1    = (const float*)d_in[11];
    const float* b1    = (const float*)d_in[12];
    const float* W2    = (const float*)d_in[13];
    const float* b2    = (const float*)d_in[14];
    const float* W3    = (const float*)d_in[15];
    const float* b3    = (const float*)d_in[16];

    size_t smemB = SMEM_B_FLOATS * sizeof(float);
    cudaFuncSetAttribute(kernelA, cudaFuncAttributeMaxDynamicSharedMemorySize, SMEM_A);
    cudaFuncSetAttribute(kernelB, cudaFuncAttributeMaxDynamicSharedMemorySize, (int)smemB);

    kernelM<<<82, 256>>>(Wq, bq, Wk, bk, Wv, bv, W1, b1);
    kernelA<<<152, 256, SMEM_A>>>(x, W_in, b_in, W_c, b_c);
    kernelB<<<152, 512, smemB>>>(W2, b2, W3, b3, (float*)d_out);
}

// round 15
// speedup vs baseline: 1.4925x; 1.0249x over previous
#include <cuda_runtime.h>
#include <cuda_bf16.h>
#include <cstdint>

#define T 48
#define E 32
#define C0 64
#define C1 64
#define H1 256
#define H2 128
#define NPRED 12
#define SEQS (16 * 2048)
#define NQ (SEQS / 4)

__device__ float g_last[SEQS * C1];    // holds r (ctx folded into MLP weights)
__device__ float g_M[4096];            // M = Wq . Wk^T  [j][ci]
__device__ float g_W1p[64 * 256];      // W1' = Wv . W1
__device__ float g_b1p[256];           // b1' = b1 + bv . W1
__device__ float g_WKBQ[64];
__device__ float g_WQBK[64];
__device__ float g_C0v[1];

// ---- kernel A smem byte offsets (4 seqs / iter) ----
#define O_WIN_H 0        // WinT [64n][40k] bf16, stride 80B
#define O_WIN_L 5120
#define O_WC_H  10240    // WcT 3 x [64n][72k] bf16, stride 144B, dt stride 9216
#define O_WC_L  37888
#define O_X_H   65536    // x [192r][40k] bf16, stride 80B
#define O_X_L   80896
#define O_H_H   96256    // h padded [4][50][72] bf16, row stride 144B, seq stride 7200
#define O_H_L   125056
#define O_HC    153856   // hc fp32 [192][68]
#define O_LAST  206080   // fp32 [4][64]
#define O_QK    207104   // fp32 [4][64]
#define O_SC    208128   // fp32 [192]
#define O_ATTN  208896   // fp32 [4][48]
#define O_C0    209664
#define O_WKBQ  209680
#define O_WQBK  209936
#define O_BIAS  210192   // fp32: bin@0 bc@64
#define O_M     210704   // fp32 [64][65]
#define SMEM_A  227344

// ---------------- warp MMA helpers ----------------
__device__ __forceinline__ uint32_t smem_u32(const void* p) {
    uint32_t a;
    asm("{ .reg .u64 t; cvta.to.shared.u64 t, %1; cvt.u32.u64 %0, t; }" : "=r"(a) : "l"(p));
    return a;
}
__device__ __forceinline__ void hmma(float* d, const uint32_t* a, const uint32_t* b) {
    asm volatile(
        "mma.sync.aligned.m16n8k16.row.col.f32.bf16.bf16.f32 "
        "{%0,%1,%2,%3}, {%4,%5,%6,%7}, {%8,%9}, {%0,%1,%2,%3};"
        : "+f"(d[0]), "+f"(d[1]), "+f"(d[2]), "+f"(d[3])
        : "r"(a[0]), "r"(a[1]), "r"(a[2]), "r"(a[3]), "r"(b[0]), "r"(b[1]));
}
__device__ __forceinline__ void ldA(uint32_t* f, uint32_t rowbase, int stride, int k0, int lane) {
    int g = lane >> 3;
    uint32_t addr = rowbase + (uint32_t)(((lane & 7) + ((g & 1) << 3)) * stride
                                         + (k0 + ((g >> 1) << 3)) * 2);
    asm volatile("ldmatrix.sync.aligned.m8n8.x4.shared.b16 {%0,%1,%2,%3}, [%4];"
                 : "=r"(f[0]), "=r"(f[1]), "=r"(f[2]), "=r"(f[3]) : "r"(addr));
}
__device__ __forceinline__ void ldB(uint32_t* f, uint32_t base, int stride, int cb, int k0, int lane) {
    uint32_t addr = base + (uint32_t)((cb + (lane & 7)) * stride + k0 * 2
                                      + (((lane >> 3) & 1) << 4));
    asm volatile("ldmatrix.sync.aligned.m8n8.x2.shared.b16 {%0,%1}, [%2];"
                 : "=r"(f[0]), "=r"(f[1]) : "r"(addr));
}
__device__ __forceinline__ void splitw(float a, float b, uint32_t& hw, uint32_t& lw) {
    __nv_bfloat162 H = __floats2bfloat162_rn(a, b);
    float2 F = __bfloat1622float2(H);
    __nv_bfloat162 L = __floats2bfloat162_rn(a - F.x, b - F.y);
    hw = *reinterpret_cast<uint32_t*>(&H);
    lw = *reinterpret_cast<uint32_t*>(&L);
}

// ---------------- init kernel: fold attention + ctx weights ----------------
__global__ void __launch_bounds__(256)
kernelM(const float* __restrict__ Wq, const float* __restrict__ bq,
        const float* __restrict__ Wk, const float* __restrict__ bk,
        const float* __restrict__ Wv, const float* __restrict__ bv,
        const float* __restrict__ W1, const float* __restrict__ b1)
{
    int idx = blockIdx.x * 256 + threadIdx.x;
    if (idx < 4096) {                       // M = Wq . Wk^T
        int j = idx >> 6, ci = idx & 63;
        float a = 0.f;
        #pragma unroll 8
        for (int co = 0; co < 64; co++) a += Wq[j * 64 + co] * Wk[ci * 64 + co];
        g_M[idx] = a;
    } else if (idx < 4096 + 16384) {        // W1' = Wv . W1
        int o = idx - 4096;
        int ci = o >> 8, n = o & 255;
        float a = 0.f;
        #pragma unroll 8
        for (int co = 0; co < 64; co++) a += Wv[ci * 64 + co] * W1[co * 256 + n];
        g_W1p[o] = a;
    } else if (idx < 20480 + 256) {         // b1' = b1 + bv . W1
        int n = idx - 20480;
        float a = b1[n];
        #pragma unroll 8
        for (int co = 0; co < 64; co++) a += bv[co] * W1[co * 256 + n];
        g_b1p[n] = a;
    } else if (idx < 20736 + 64) {          // WKBQ, WQBK
        int t2 = idx - 20736;
        float a = 0.f, b = 0.f;
        #pragma unroll 8
        for (int co = 0; co < 64; co++) {
            a += Wk[t2 * 64 + co] * bq[co];
            b += Wq[t2 * 64 + co] * bk[co];
        }
        g_WKBQ[t2] = a;
        g_WQBK[t2] = b;
    } else if (idx == 20800) {
        float c = 0.f;
        #pragma unroll 8
        for (int co = 0; co < 64; co++) c += bq[co] * bk[co];
        g_C0v[0] = c;
    }
}

// ---------------- Kernel A: rotated pipeline, 4 seqs/iter, r-output (round-11 proven) ----------------
__global__ void __launch_bounds__(256, 1)
kernelA(const float* __restrict__ x,
        const float* __restrict__ Win, const float* __restrict__ bin,
        const float* __restrict__ Wc,  const float* __restrict__ bc)
{
    extern __shared__ char smc[];
    const uint32_t smb = smem_u32(smc);
    const int tid  = threadIdx.x;
    const int wid  = tid >> 5;
    const int lane = tid & 31;
    const int cbase = wid * 8;

    float* sBias = (float*)(smc + O_BIAS);
    float* sLast = (float*)(smc + O_LAST);
    float* sQK   = (float*)(smc + O_QK);
    float* sSC   = (float*)(smc + O_SC);
    float* sAttn = (float*)(smc + O_ATTN);
    float* sC0   = (float*)(smc + O_C0);
    float* sWKBQ = (float*)(smc + O_WKBQ);
    float* sWQBK = (float*)(smc + O_WQBK);
    float* sHC   = (float*)(smc + O_HC);
    float* sM    = (float*)(smc + O_M);      // [64][65]

    // ---- stage weights ----
    for (int i = tid; i < 2048; i += 256) {
        int e = i >> 6, c = i & 63;
        float w = Win[i];
        __nv_bfloat16 h = __float2bfloat16(w);
        *(__nv_bfloat16*)(smc + O_WIN_H + c * 80 + e * 2) = h;
        *(__nv_bfloat16*)(smc + O_WIN_L + c * 80 + e * 2) =
            __float2bfloat16(w - __bfloat162float(h));
    }
    for (int i = tid; i < 12288; i += 256) {
        int dt = i >> 12, r = i & 4095, ci = r >> 6, co = r & 63;
        float w = Wc[i];
        __nv_bfloat16 h = __float2bfloat16(w);
        uint32_t o = dt * 9216 + co * 144 + ci * 2;
        *(__nv_bfloat16*)(smc + O_WC_H + o) = h;
        *(__nv_bfloat16*)(smc + O_WC_L + o) = __float2bfloat16(w - __bfloat162float(h));
    }
    for (int i = tid; i < 4096; i += 256) {     // M -> smem, re-stride to 65
        int j = i >> 6, ci = i & 63;
        sM[j * 65 + ci] = g_M[i];
    }
    if (tid < 64) {
        sWKBQ[tid] = g_WKBQ[tid];
        sWQBK[tid] = g_WQBK[tid];
        sBias[tid]      = bin[tid];
        sBias[64 + tid] = bc[tid];
    }
    if (tid == 128) sC0[0] = g_C0v[0];
    for (int i = tid; i < 14400; i += 256) ((uint32_t*)(smc + O_H_H))[i] = 0;
    __syncthreads();

    // ---- prologue: stage x(quad0), GEMM1(quad0) -> h ----
    {
        const float4* xg = (const float4*)(x + (size_t)blockIdx.x * 4 * (T * E));
        for (int i = tid; i < 1536; i += 256) {
            float4 v = xg[i];
            int row = i >> 3, e4 = i & 7;
            uint32_t o = (uint32_t)(row * 80 + e4 * 8);
            uint32_t h0, l0, h1, l1;
            splitw(v.x, v.y, h0, l0);
            splitw(v.z, v.w, h1, l1);
            *(uint32_t*)(smc + O_X_H + o)     = h0;
            *(uint32_t*)(smc + O_X_H + o + 4) = h1;
            *(uint32_t*)(smc + O_X_L + o)     = l0;
            *(uint32_t*)(smc + O_X_L + o + 4) = l1;
        }
    }
    __syncthreads();
    {
        float acc[12][4] = {};
        #pragma unroll
        for (int k = 0; k < 2; k++) {
            int k0 = k * 16;
            uint32_t bh[2], bl[2];
            ldB(bh, smb + O_WIN_H, 80, cbase, k0, lane);
            ldB(bl, smb + O_WIN_L, 80, cbase, k0, lane);
            #pragma unroll
            for (int mt = 0; mt < 12; mt++) {
                uint32_t ah[4], al[4];
                ldA(ah, smb + O_X_H + mt * 16 * 80, 80, k0, lane);
                ldA(al, smb + O_X_L + mt * 16 * 80, 80, k0, lane);
                hmma(acc[mt], ah, bh);
                hmma(acc[mt], ah, bl);
                hmma(acc[mt], al, bh);
            }
        }
        int c = cbase + (lane & 3) * 2;
        float b0 = sBias[c], b1v = sBias[c + 1];
        #pragma unroll
        for (int mt = 0; mt < 12; mt++) {
            int s = mt / 3, j = mt % 3;
            int t0 = j * 16 + (lane >> 2), t1 = t0 + 8;
            uint32_t h0, l0, h1, l1;
            splitw(acc[mt][0] + b0, acc[mt][1] + b1v, h0, l0);
            splitw(acc[mt][2] + b0, acc[mt][3] + b1v, h1, l1);
            uint32_t o0 = (uint32_t)(s * 7200 + (t0 + 1) * 144 + c * 2);
            uint32_t o1 = (uint32_t)(s * 7200 + (t1 + 1) * 144 + c * 2);
            *(uint32_t*)(smc + O_H_H + o0) = h0;
            *(uint32_t*)(smc + O_H_L + o0) = l0;
            *(uint32_t*)(smc + O_H_H + o1) = h1;
            *(uint32_t*)(smc + O_H_L + o1) = l1;
        }
    }
    __syncthreads();

    // ---- main loop ----
    for (int quad = blockIdx.x; quad < NQ; quad += gridDim.x) {
        const int seq0 = quad * 4;
        const int nquad = quad + gridDim.x;
        const bool hasnext = nquad < NQ;

        float4 nx[6];
        if (hasnext) {
            const float4* xg = (const float4*)(x + (size_t)nquad * 4 * (T * E));
            #pragma unroll
            for (int j = 0; j < 6; j++) nx[j] = xg[tid + j * 256];
        }

        // ---- GEMM2: hc = relu(conv(h) + bc), fp32 [192][68] ----
        {
            float acc[12][4] = {};
            #pragma unroll
            for (int dt = 0; dt < 3; dt++) {
                #pragma unroll
                for (int k = 0; k < 4; k++) {
                    int k0 = k * 16;
                    uint32_t bh[2], bl[2];
                    ldB(bh, smb + O_WC_H + dt * 9216, 144, cbase, k0, lane);
                    ldB(bl, smb + O_WC_L + dt * 9216, 144, cbase, k0, lane);
                    #pragma unroll
                    for (int mt = 0; mt < 12; mt++) {
                        int s = mt / 3, j = mt % 3;
                        uint32_t rb = (uint32_t)(s * 7200 + (j * 16 + dt) * 144);
                        uint32_t ah[4], al[4];
                        ldA(ah, smb + O_H_H + rb, 144, k0, lane);
                        ldA(al, smb + O_H_L + rb, 144, k0, lane);
                        hmma(acc[mt], ah, bh);
                        hmma(acc[mt], ah, bl);
                        hmma(acc[mt], al, bh);
                    }
                }
            }
            int c = cbase + (lane & 3) * 2;
            float b0 = sBias[64 + c], b1v = sBias[64 + c + 1];
            #pragma unroll
            for (int mt = 0; mt < 12; mt++) {
                int s = mt / 3, j = mt % 3;
                int t0 = j * 16 + (lane >> 2), t1 = t0 + 8;
                int g0 = s * 48 + t0, g1 = s * 48 + t1;
                float v0 = fmaxf(acc[mt][0] + b0, 0.f), v1 = fmaxf(acc[mt][1] + b1v, 0.f);
                float v2 = fmaxf(acc[mt][2] + b0, 0.f), v3 = fmaxf(acc[mt][3] + b1v, 0.f);
                sHC[g0 * 68 + c]     = v0;
                sHC[g0 * 68 + c + 1] = v1;
                sHC[g1 * 68 + c]     = v2;
                sHC[g1 * 68 + c + 1] = v3;
                if (t1 == 47) {
                    sLast[s * 64 + c]     = v2;
                    sLast[s * 64 + c + 1] = v3;
                }
            }
        }

        if (hasnext) {
            #pragma unroll
            for (int j = 0; j < 6; j++) {
                float4 v = nx[j];
                int idx = tid + j * 256;
                int row = idx >> 3, e4 = idx & 7;
                uint32_t o = (uint32_t)(row * 80 + e4 * 8);
                uint32_t h0, l0, h1, l1;
                splitw(v.x, v.y, h0, l0);
                splitw(v.z, v.w, h1, l1);
                *(uint32_t*)(smc + O_X_H + o)     = h0;
                *(uint32_t*)(smc + O_X_H + o + 4) = h1;
                *(uint32_t*)(smc + O_X_L + o)     = l0;
                *(uint32_t*)(smc + O_X_L + o + 4) = l1;
            }
        }
        __syncthreads();

        // ---- GEMM1(next quad): compute only ----
        float acc1[12][4] = {};
        if (hasnext) {
            #pragma unroll
            for (int k = 0; k < 2; k++) {
                int k0 = k * 16;
                uint32_t bh[2], bl[2];
                ldB(bh, smb + O_WIN_H, 80, cbase, k0, lane);
                ldB(bl, smb + O_WIN_L, 80, cbase, k0, lane);
                #pragma unroll
                for (int mt = 0; mt < 12; mt++) {
                    uint32_t ah[4], al[4];
                    ldA(ah, smb + O_X_H + mt * 16 * 80, 80, k0, lane);
                    ldA(al, smb + O_X_L + mt * 16 * 80, 80, k0, lane);
                    hmma(acc1[mt], ah, bh);
                    hmma(acc1[mt], ah, bl);
                    hmma(acc1[mt], al, bh);
                }
            }
        }

        // ---- qk = M^T hc_last + wkbq (smem M) ----
        {
            int s = tid >> 6, c = tid & 63;
            const float* hl = sLast + s * 64;
            float a = sWKBQ[c];
            #pragma unroll 8
            for (int j = 0; j < 64; j++) a += hl[j] * sM[j * 65 + c];
            sQK[s * 64 + c] = a;
        }
        __syncthreads();

        // ---- raw scores: float4 dot over [68]-stride rows ----
        if (tid < 192) {
            int row = tid, s = row / 48;
            const float4* qk4 = (const float4*)(sQK + s * 64);
            const float4* hr4 = (const float4*)(sHC + row * 68);
            float p = 0.f;
            #pragma unroll
            for (int j = 0; j < 16; j++) {
                float4 a4 = qk4[j], b4 = hr4[j];
                p += a4.x * b4.x + a4.y * b4.y + a4.z * b4.z + a4.w * b4.w;
            }
            sSC[row] = p;
        }
        __syncthreads();

        // ---- softmax over 48 per seq (warp s), qb inline ----
        if (wid < 4) {
            const float* hl = sLast + wid * 64;
            float qb = hl[lane] * sWQBK[lane] + hl[lane + 32] * sWQBK[lane + 32];
            #pragma unroll
            for (int o = 16; o > 0; o >>= 1) qb += __shfl_xor_sync(0xffffffffu, qb, o);
            qb += sC0[0];
            int base = wid * 48;
            float a  = (sSC[base + lane] + qb) * 0.125f;
            float b2 = (lane < 16) ? (sSC[base + 32 + lane] + qb) * 0.125f : -1e30f;
            float m = fmaxf(a, b2);
            #pragma unroll
            for (int o = 16; o > 0; o >>= 1) m = fmaxf(m, __shfl_xor_sync(0xffffffffu, m, o));
            float ea = __expf(a - m);
            float eb = (lane < 16) ? __expf(b2 - m) : 0.f;
            float sden = ea + eb;
            #pragma unroll
            for (int o = 16; o > 0; o >>= 1) sden += __shfl_xor_sync(0xffffffffu, sden, o);
            float inv = 1.f / sden;
            sAttn[base + lane] = ea * inv;
            if (lane < 16) sAttn[base + 32 + lane] = eb * inv;
        }
        __syncthreads();

        // ---- r = attn^T . hc  -> g_last directly (ctx folded into MLP) ----
        {
            int s = tid >> 6, c = tid & 63;
            const float* at = sAttn + s * 48;
            const float* hb = sHC + s * 48 * 68 + c;
            float a = 0.f;
            #pragma unroll
            for (int t = 0; t < 48; t++) a += at[t] * hb[t * 68];
            g_last[(size_t)(seq0 + s) * 64 + c] = a;
        }

        // ---- ep1(next quad) ----
        if (hasnext) {
            int c = cbase + (lane & 3) * 2;
            float b0 = sBias[c], b1v = sBias[c + 1];
            #pragma unroll
            for (int mt = 0; mt < 12; mt++) {
                int s = mt / 3, j = mt % 3;
                int t0 = j * 16 + (lane >> 2), t1 = t0 + 8;
                uint32_t h0, l0, h1, l1;
                splitw(acc1[mt][0] + b0, acc1[mt][1] + b1v, h0, l0);
                splitw(acc1[mt][2] + b0, acc1[mt][3] + b1v, h1, l1);
                uint32_t o0 = (uint32_t)(s * 7200 + (t0 + 1) * 144 + c * 2);
                uint32_t o1 = (uint32_t)(s * 7200 + (t1 + 1) * 144 + c * 2);
                *(uint32_t*)(smc + O_H_H + o0) = h0;
                *(uint32_t*)(smc + O_H_L + o0) = l0;
                *(uint32_t*)(smc + O_H_H + o1) = h1;
                *(uint32_t*)(smc + O_H_L + o1) = l1;
            }
        }
        __syncthreads();
    }
}

// ---------------- Kernel B: MLP, 512 threads, reuse-preserving conflict-free tiling ----------------
// smem floats: sW1 0 (16384), sW2 16384 (32768), sb1 49152 (256), sb2 49408 (128),
//   sb3 49536 (16), sIn 49552 [16][65]=1040, sZ1 50592 [16][264]=4224 (stride mult of 4!),
//   sZ2 54816 [16][132]=2112  -> 56928 floats = 227712 B
#define SMEM_B_FLOATS 56928

__global__ void __launch_bounds__(512, 1)
kernelB(const float* __restrict__ W2, const float* __restrict__ b2,
        const float* __restrict__ W3, const float* __restrict__ b3,
        float* __restrict__ out)
{
    extern __shared__ float sm[];
    float* sW1 = sm;
    float* sW2 = sm + 16384;
    float* sb1 = sm + 49152;
    float* sb2 = sm + 49408;
    float* sb3 = sm + 49536;
    float* sIn = sm + 49552;   // [16][65]
    float* sZ1 = sm + 50592;   // [16][264]  (264 % 4 == 0 -> float4-aligned rows)
    float* sZ2 = sm + 54816;   // [16][132]

    const int tid  = threadIdx.x;
    const int wid  = tid >> 5;
    const int lane = tid & 31;

    for (int i = tid; i < 16384; i += 512) sW1[i] = g_W1p[i];
    for (int i = tid; i < 32768; i += 512) sW2[i] = W2[i];
    if (tid < 256) sb1[tid] = g_b1p[tid];
    else if (tid < 384) sb2[tid - 256] = b2[tid - 256];
    else if (tid < 396) sb3[tid - 384] = b3[tid - 384];
    __syncthreads();

    // z1: warp -> 32-col group (wid&7) x 8-row group (wid>>3)
    //     lane -> float4 col (lane&7: 8 float4 = 128B conflict-free), row lane>>3 (+4)
    const int z1_cb = (wid & 7) * 32;
    const int z1_c4 = lane & 7;
    const int z1_r  = (wid >> 3) * 8 + (lane >> 3);   // rows z1_r, z1_r+4
    // z2: warp -> 32-col group (wid&3) x 4-row group (wid>>2)
    const int z2_cb = (wid & 3) * 32;
    const int z2_c4 = lane & 7;
    const int z2_r  = (wid >> 2) * 4 + (lane >> 3);   // one row

    for (int base = blockIdx.x * 16; base < SEQS; base += gridDim.x * 16) {
        // stage 16 rows of g_last -> sIn [16][65]
        if (tid < 256) {
            float4 v = ((const float4*)(g_last + (size_t)base * C1))[tid];
            int row = tid >> 4, e4 = tid & 15;
            float* d = sIn + row * 65 + e4 * 4;
            d[0] = v.x; d[1] = v.y; d[2] = v.z; d[3] = v.w;
        }
        __syncthreads();

        // ---- z1 = relu(in @ W1' + b1'): 16 x 256, 2 rows x 4 cols / thread ----
        {
            float4 bb = ((const float4*)(sb1 + z1_cb))[z1_c4];
            float a0[4] = {bb.x, bb.y, bb.z, bb.w};
            float a1[4] = {bb.x, bb.y, bb.z, bb.w};
            const float* in0 = sIn + z1_r * 65;
            const float* in1 = sIn + (z1_r + 4) * 65;
            #pragma unroll 8
            for (int f = 0; f < 64; f++) {
                float4 w = ((const float4*)(sW1 + f * H1 + z1_cb))[z1_c4];
                float x0 = in0[f];
                float x1 = in1[f];
                a0[0] += x0 * w.x; a0[1] += x0 * w.y; a0[2] += x0 * w.z; a0[3] += x0 * w.w;
                a1[0] += x1 * w.x; a1[1] += x1 * w.y; a1[2] += x1 * w.z; a1[3] += x1 * w.w;
            }
            ((float4*)(sZ1 + z1_r * 264 + z1_cb))[z1_c4] =
                make_float4(fmaxf(a0[0], 0.f), fmaxf(a0[1], 0.f), fmaxf(a0[2], 0.f), fmaxf(a0[3], 0.f));
            ((float4*)(sZ1 + (z1_r + 4) * 264 + z1_cb))[z1_c4] =
                make_float4(fmaxf(a1[0], 0.f), fmaxf(a1[1], 0.f), fmaxf(a1[2], 0.f), fmaxf(a1[3], 0.f));
        }
        __syncthreads();

        // ---- z2 = relu(z1 @ W2 + b2): 16 x 128, 1 row x 4 cols / thread ----
        {
            float4 bb = ((const float4*)(sb2 + z2_cb))[z2_c4];
            float a[4] = {bb.x, bb.y, bb.z, bb.w};
            const float* zr = sZ1 + z2_r * 264;
            #pragma unroll 8
            for (int f = 0; f < 256; f++) {
                float4 w = ((const float4*)(sW2 + f * H2 + z2_cb))[z2_c4];
                float z = zr[f];
                a[0] += z * w.x; a[1] += z * w.y; a[2] += z * w.z; a[3] += z * w.w;
            }
            ((float4*)(sZ2 + z2_r * 132 + z2_cb))[z2_c4] =
                make_float4(fmaxf(a[0], 0.f), fmaxf(a[1], 0.f), fmaxf(a[2], 0.f), fmaxf(a[3], 0.f));
        }
        __syncthreads();

        // ---- pred = z2 @ W3 + b3: 16 x 12, transposed write; W3 via L1 ----
        if (tid < 192) {
            int r = tid / 12, p = tid % 12;
            const float* zr = sZ2 + r * 132;
            float a = sb3[p];
            #pragma unroll 16
            for (int f = 0; f < 128; f++) a += zr[f] * __ldg(&W3[f * NPRED + p]);
            int seqr = base + r;
            int bb = seqr >> 11;
            int nn = seqr & 2047;
            out[(size_t)bb * (NPRED * 2048) + p * 2048 + nn] = a;
        }
        __syncthreads();
    }
}

extern "C" void kernel_launch(void* const* d_in, const int* in_sizes, int n_in,
                              void* d_out, int out_size)
{
    const float* x     = (const float*)d_in[0];
    const float* W_in  = (const float*)d_in[1];
    const float* b_in  = (const float*)d_in[2];
    const float* W_c   = (const float*)d_in[3];
    const float* b_c   = (const float*)d_in[4];
    const float* Wq    = (const float*)d_in[5];
    const float* bq    = (const float*)d_in[6];
    const float* Wk    = (const float*)d_in[7];
    const float* bk    = (const float*)d_in[8];
    const float* Wv    = (const float*)d_in[9];
    const float* bv    = (const float*)d_in[10];
    const float* W1    = (const float*)d_in[11];
    const float* b1    = (const float*)d_in[12];
    const float* W2    = (const float*)d_in[13];
    const float* b2    = (const float*)d_in[14];
    const float* W3    = (const float*)d_in[15];
    const float* b3    = (const float*)d_in[16];

    size_t smemB = SMEM_B_FLOATS * sizeof(float);
    cudaFuncSetAttribute(kernelA, cudaFuncAttributeMaxDynamicSharedMemorySize, SMEM_A);
    cudaFuncSetAttribute(kernelB, cudaFuncAttributeMaxDynamicSharedMemorySize, (int)smemB);

    kernelM<<<82, 256>>>(Wq, bq, Wk, bk, Wv, bv, W1, b1);
    kernelA<<<152, 256, SMEM_A>>>(x, W_in, b_in, W_c, b_c);
    kernelB<<<152, 512, smemB>>>(W2, b2, W3, b3, (float*)d_out);
}